// round 13
// baseline (speedup 1.0000x reference)
#include <cuda_runtime.h>
#include <cuda_fp16.h>
#include <cuda_bf16.h>
#include <cstdint>

// Problem constants (fixed shapes from reference)
#define BATCH      16
#define TLEN       1024
#define CCH        32
#define TC         (TLEN * CCH)        // 32768
#define KDIM       128
#define S_MAIN     128
#define NB_PATCH   400
#define P_TOP      60
#define P_OUT      (NB_PATCH + P_TOP)  // 460
#define STRETCH    8

#define THREADS    512                 // 16 warps; each warp owns up to 2 tasks
#define TPB        32                  // tasks (p columns) per block
#define SB         17                  // s_res row stride (conflict-free)
#define MAIN_PB    ((NB_PATCH + TPB - 1) / TPB)  // 13 (last width 16)
#define TOP_PB     ((P_TOP + TPB - 1) / TPB)     // 2  (last width 28)
#define MAIN_BLOCKS (S_MAIN * MAIN_PB) // 1664
#define TOP_BLOCKS  (TLEN * TOP_PB)    // 2048
#define ALL_BLOCKS  (MAIN_BLOCKS + TOP_BLOCKS)   // 3712

// Scratch: transposed fp16 x, xTh[tc][b]. One gather index pulls 16 halves
// = 32B (one L2 sector) holding all 16 batch values.
__device__ __align__(32) __half g_xTh[TC * BATCH];

// --------------------------------------------------------------------------
// Kernel 1: transpose + fp16-quantize x [B, T*C] -> xTh [T*C, B]
// --------------------------------------------------------------------------
__global__ void transpose_x_kernel(const float* __restrict__ x) {
    int tc = blockIdx.x * blockDim.x + threadIdx.x;
    if (tc >= TC) return;
    __half2 h[8];
#pragma unroll
    for (int b = 0; b < 8; b++) {
        h[b] = __floats2half2_rn(x[(2 * b) * TC + tc], x[(2 * b + 1) * TC + tc]);
    }
    uint4* dst = reinterpret_cast<uint4*>(g_xTh + tc * BATCH);
    unsigned int* hu = reinterpret_cast<unsigned int*>(h);
    dst[0] = make_uint4(hu[0], hu[1], hu[2], hu[3]);
    dst[1] = make_uint4(hu[4], hu[5], hu[6], hu[7]);
}

__device__ __forceinline__ float lrelu03(float v) {
    return (v > 0.f) ? v : 0.3f * v;
}

// --------------------------------------------------------------------------
// Kernel 2: fused main + top patch layers.  (R10 geometry + dead-chain skip)
// Block = 16 warps covering 32 consecutive p of one (s|t) row.
// Warp w owns tasks pA = w and pB = w+16: two INDEPENDENT gather->FMA
// chains per warp (structural MLP ~2x). B chain is skipped warp-uniformly
// when pB >= width (no wasted gathers on narrow blocks).
// Lane = (q = lane>>2, c = lane&3):
//   - idx/W per chain: int4/float4 at [m*8+q] (128B per warp-load, 1 wf),
//   - gathers: quad q fetches row idx, lane reads 8B (batches 4c..4c+3),
//   - reduce via shfl_xor(4,8,16); q==0 lanes hold all 16 batches,
//   - padded smem stage; store: warp = batch, 32 lanes = 32 consecutive p
//     (128B rows, main repeated x8 along time).
// --------------------------------------------------------------------------
__global__ __launch_bounds__(THREADS, 2) void patchy_kernel(
    const float* __restrict__ W_main, const float* __restrict__ b_main,
    const float* __restrict__ W_top,  const float* __restrict__ b_top,
    const int*   __restrict__ idx_main, const int* __restrict__ idx_top,
    float* __restrict__ out)
{
    __shared__ float s_res[TPB * SB];

    const int tid  = threadIdx.x;
    const int w    = tid >> 5;       // warp id: local pA (compute) / batch (store)
    const int lane = tid & 31;
    const int q    = lane >> 2;      // quad: sub-index group
    const int c    = lane & 3;       // component: batches 4c..4c+3
    const bool is_main = (blockIdx.x < MAIN_BLOCKS);

    int st, p0, width;
    const int*   gi;
    const float* gw;
    const float* gb;
    if (is_main) {
        st    = blockIdx.x / MAIN_PB;
        p0    = (blockIdx.x - st * MAIN_PB) * TPB;
        width = min(TPB, NB_PATCH - p0);
        const long base = ((long)st * NB_PATCH + p0) * KDIM;
        gi = idx_main + base;
        gw = W_main   + base;
        gb = b_main   + st * NB_PATCH + p0;
    } else {
        const int b2 = blockIdx.x - MAIN_BLOCKS;
        st    = b2 >> 1;
        p0    = (b2 & 1) * TPB;
        width = min(TPB, P_TOP - p0);
        const long base = ((long)st * P_TOP + p0) * KDIM;
        gi = idx_top + base;
        gw = W_top   + base;
        gb = b_top   + st * P_TOP + p0;
    }

    const int  pA   = w;
    const int  pB   = w + 16;
    const bool hasB = (pB < width);   // warp-uniform

    {
        const int4*   ipA = reinterpret_cast<const int4*>(gi + pA * KDIM);
        const float4* wpA = reinterpret_cast<const float4*>(gw + pA * KDIM);
        const int4*   ipB = reinterpret_cast<const int4*>(gi + pB * KDIM);
        const float4* wpB = reinterpret_cast<const float4*>(gw + pB * KDIM);
        const uint2* __restrict__ xT2 = reinterpret_cast<const uint2*>(g_xTh);

        float4 accA = make_float4(0.f, 0.f, 0.f, 0.f);
        float4 accB = make_float4(0.f, 0.f, 0.f, 0.f);

        if (hasB) {
            // ---- two independent chains interleaved ----
#pragma unroll
            for (int m = 0; m < 4; m++) {
                const int4 IA = ipA[m * 8 + q];
                const int4 IB = ipB[m * 8 + q];

                const uint2 gA0 = xT2[IA.x * 4 + c];
                const uint2 gA1 = xT2[IA.y * 4 + c];
                const uint2 gA2 = xT2[IA.z * 4 + c];
                const uint2 gA3 = xT2[IA.w * 4 + c];
                const uint2 gB0 = xT2[IB.x * 4 + c];
                const uint2 gB1 = xT2[IB.y * 4 + c];
                const uint2 gB2 = xT2[IB.z * 4 + c];
                const uint2 gB3 = xT2[IB.w * 4 + c];

                const float4 WA = wpA[m * 8 + q];
                const float4 WB = wpB[m * 8 + q];

                {
                    const float2 l0 = __half22float2(*reinterpret_cast<const __half2*>(&gA0.x));
                    const float2 h0 = __half22float2(*reinterpret_cast<const __half2*>(&gA0.y));
                    accA.x = fmaf(l0.x, WA.x, accA.x); accA.y = fmaf(l0.y, WA.x, accA.y);
                    accA.z = fmaf(h0.x, WA.x, accA.z); accA.w = fmaf(h0.y, WA.x, accA.w);
                    const float2 l1 = __half22float2(*reinterpret_cast<const __half2*>(&gA1.x));
                    const float2 h1 = __half22float2(*reinterpret_cast<const __half2*>(&gA1.y));
                    accA.x = fmaf(l1.x, WA.y, accA.x); accA.y = fmaf(l1.y, WA.y, accA.y);
                    accA.z = fmaf(h1.x, WA.y, accA.z); accA.w = fmaf(h1.y, WA.y, accA.w);
                    const float2 l2 = __half22float2(*reinterpret_cast<const __half2*>(&gA2.x));
                    const float2 h2 = __half22float2(*reinterpret_cast<const __half2*>(&gA2.y));
                    accA.x = fmaf(l2.x, WA.z, accA.x); accA.y = fmaf(l2.y, WA.z, accA.y);
                    accA.z = fmaf(h2.x, WA.z, accA.z); accA.w = fmaf(h2.y, WA.z, accA.w);
                    const float2 l3 = __half22float2(*reinterpret_cast<const __half2*>(&gA3.x));
                    const float2 h3 = __half22float2(*reinterpret_cast<const __half2*>(&gA3.y));
                    accA.x = fmaf(l3.x, WA.w, accA.x); accA.y = fmaf(l3.y, WA.w, accA.y);
                    accA.z = fmaf(h3.x, WA.w, accA.z); accA.w = fmaf(h3.y, WA.w, accA.w);
                }
                {
                    const float2 l0 = __half22float2(*reinterpret_cast<const __half2*>(&gB0.x));
                    const float2 h0 = __half22float2(*reinterpret_cast<const __half2*>(&gB0.y));
                    accB.x = fmaf(l0.x, WB.x, accB.x); accB.y = fmaf(l0.y, WB.x, accB.y);
                    accB.z = fmaf(h0.x, WB.x, accB.z); accB.w = fmaf(h0.y, WB.x, accB.w);
                    const float2 l1 = __half22float2(*reinterpret_cast<const __half2*>(&gB1.x));
                    const float2 h1 = __half22float2(*reinterpret_cast<const __half2*>(&gB1.y));
                    accB.x = fmaf(l1.x, WB.y, accB.x); accB.y = fmaf(l1.y, WB.y, accB.y);
                    accB.z = fmaf(h1.x, WB.y, accB.z); accB.w = fmaf(h1.y, WB.y, accB.w);
                    const float2 l2 = __half22float2(*reinterpret_cast<const __half2*>(&gB2.x));
                    const float2 h2 = __half22float2(*reinterpret_cast<const __half2*>(&gB2.y));
                    accB.x = fmaf(l2.x, WB.z, accB.x); accB.y = fmaf(l2.y, WB.z, accB.y);
                    accB.z = fmaf(h2.x, WB.z, accB.z); accB.w = fmaf(h2.y, WB.z, accB.w);
                    const float2 l3 = __half22float2(*reinterpret_cast<const __half2*>(&gB3.x));
                    const float2 h3 = __half22float2(*reinterpret_cast<const __half2*>(&gB3.y));
                    accB.x = fmaf(l3.x, WB.w, accB.x); accB.y = fmaf(l3.y, WB.w, accB.y);
                    accB.z = fmaf(h3.x, WB.w, accB.z); accB.w = fmaf(h3.y, WB.w, accB.w);
                }
            }
        } else {
            // ---- single chain (narrow block) ----
#pragma unroll
            for (int m = 0; m < 4; m++) {
                const int4 IA = ipA[m * 8 + q];

                const uint2 gA0 = xT2[IA.x * 4 + c];
                const uint2 gA1 = xT2[IA.y * 4 + c];
                const uint2 gA2 = xT2[IA.z * 4 + c];
                const uint2 gA3 = xT2[IA.w * 4 + c];

                const float4 WA = wpA[m * 8 + q];

                const float2 l0 = __half22float2(*reinterpret_cast<const __half2*>(&gA0.x));
                const float2 h0 = __half22float2(*reinterpret_cast<const __half2*>(&gA0.y));
                accA.x = fmaf(l0.x, WA.x, accA.x); accA.y = fmaf(l0.y, WA.x, accA.y);
                accA.z = fmaf(h0.x, WA.x, accA.z); accA.w = fmaf(h0.y, WA.x, accA.w);
                const float2 l1 = __half22float2(*reinterpret_cast<const __half2*>(&gA1.x));
                const float2 h1 = __half22float2(*reinterpret_cast<const __half2*>(&gA1.y));
                accA.x = fmaf(l1.x, WA.y, accA.x); accA.y = fmaf(l1.y, WA.y, accA.y);
                accA.z = fmaf(h1.x, WA.y, accA.z); accA.w = fmaf(h1.y, WA.y, accA.w);
                const float2 l2 = __half22float2(*reinterpret_cast<const __half2*>(&gA2.x));
                const float2 h2 = __half22float2(*reinterpret_cast<const __half2*>(&gA2.y));
                accA.x = fmaf(l2.x, WA.z, accA.x); accA.y = fmaf(l2.y, WA.z, accA.y);
                accA.z = fmaf(h2.x, WA.z, accA.z); accA.w = fmaf(h2.y, WA.z, accA.w);
                const float2 l3 = __half22float2(*reinterpret_cast<const __half2*>(&gA3.x));
                const float2 h3 = __half22float2(*reinterpret_cast<const __half2*>(&gA3.y));
                accA.x = fmaf(l3.x, WA.w, accA.x); accA.y = fmaf(l3.y, WA.w, accA.y);
                accA.z = fmaf(h3.x, WA.w, accA.z); accA.w = fmaf(h3.y, WA.w, accA.w);
            }
        }

        // Reduce across the 8 quads.
#pragma unroll
        for (int mask = 4; mask <= 16; mask <<= 1) {
            accA.x += __shfl_xor_sync(0xffffffffu, accA.x, mask);
            accA.y += __shfl_xor_sync(0xffffffffu, accA.y, mask);
            accA.z += __shfl_xor_sync(0xffffffffu, accA.z, mask);
            accA.w += __shfl_xor_sync(0xffffffffu, accA.w, mask);
        }
        if (hasB) {
#pragma unroll
            for (int mask = 4; mask <= 16; mask <<= 1) {
                accB.x += __shfl_xor_sync(0xffffffffu, accB.x, mask);
                accB.y += __shfl_xor_sync(0xffffffffu, accB.y, mask);
                accB.z += __shfl_xor_sync(0xffffffffu, accB.z, mask);
                accB.w += __shfl_xor_sync(0xffffffffu, accB.w, mask);
            }
        }

        if (q == 0) {
            {
                const float bias = gb[pA];
                float* r = s_res + pA * SB + c * 4;
                float vx = accA.x + bias, vy = accA.y + bias;
                float vz = accA.z + bias, vw = accA.w + bias;
                r[0] = lrelu03(vx);
                r[1] = lrelu03(vy);
                r[2] = lrelu03(vz);
                r[3] = lrelu03(vw);
            }
            if (hasB) {
                const float bias = gb[pB];
                float* r = s_res + pB * SB + c * 4;
                float vx = accB.x + bias, vy = accB.y + bias;
                float vz = accB.z + bias, vw = accB.w + bias;
                r[0] = lrelu03(vx);
                r[1] = lrelu03(vy);
                r[2] = lrelu03(vz);
                r[3] = lrelu03(vw);
            }
        }
    }
    __syncthreads();

    // ---- Coalesced store: warp = batch, 32 lanes = 32 consecutive p ----
    {
        if (lane < width) {
            const float y = s_res[lane * SB + w];   // stride-17 -> conflict-free
            if (is_main) {
                long o = (long)w * TLEN * P_OUT
                       + (long)(st * STRETCH) * P_OUT + p0 + lane;
#pragma unroll
                for (int r = 0; r < STRETCH; r++) {
                    out[o + (long)r * P_OUT] = y;   // 128B rows per STG
                }
            } else {
                out[(long)w * TLEN * P_OUT + (long)st * P_OUT
                    + NB_PATCH + p0 + lane] = y;
            }
        }
    }
}

// --------------------------------------------------------------------------
// Inputs (metadata order): x, W_main, b_main, W_top, b_top, idx_main, idx_top
// --------------------------------------------------------------------------
extern "C" void kernel_launch(void* const* d_in, const int* in_sizes, int n_in,
                              void* d_out, int out_size) {
    const float* x        = (const float*)d_in[0];
    const float* W_main   = (const float*)d_in[1];
    const float* b_main   = (const float*)d_in[2];
    const float* W_top    = (const float*)d_in[3];
    const float* b_top    = (const float*)d_in[4];
    const int*   idx_main = (const int*)  d_in[5];
    const int*   idx_top  = (const int*)  d_in[6];
    float* out = (float*)d_out;

    transpose_x_kernel<<<(TC + 255) / 256, 256>>>(x);

    patchy_kernel<<<ALL_BLOCKS, THREADS>>>(W_main, b_main, W_top, b_top,
                                           idx_main, idx_top, out);
}

// round 14
// speedup vs baseline: 1.4918x; 1.4918x over previous
#include <cuda_runtime.h>
#include <cuda_fp16.h>
#include <cuda_bf16.h>
#include <cstdint>

// Problem constants (fixed shapes from reference)
#define BATCH      16
#define TLEN       1024
#define CCH        32
#define TC         (TLEN * CCH)        // 32768
#define KDIM       128
#define S_MAIN     128
#define NB_PATCH   400
#define P_TOP      60
#define P_OUT      (NB_PATCH + P_TOP)  // 460
#define STRETCH    8

#define THREADS    512                 // 16 warps; each warp owns 2 tasks
#define TPB        32                  // tasks (p columns) per block
#define SB         17                  // s_res row stride (conflict-free)
#define MAIN_PB    ((NB_PATCH + TPB - 1) / TPB)  // 13 (last width 16)
#define TOP_PB     ((P_TOP + TPB - 1) / TPB)     // 2  (last width 28)
#define MAIN_BLOCKS (S_MAIN * MAIN_PB) // 1664
#define TOP_BLOCKS  (TLEN * TOP_PB)    // 2048
#define ALL_BLOCKS  (MAIN_BLOCKS + TOP_BLOCKS)   // 3712

// Scratch: transposed fp16 x, xTh[tc][b]. One gather index pulls 16 halves
// = 32B (one L2 sector) holding all 16 batch values.
__device__ __align__(32) __half g_xTh[TC * BATCH];

// --------------------------------------------------------------------------
// Kernel 1: transpose + fp16-quantize x [B, T*C] -> xTh [T*C, B]
// --------------------------------------------------------------------------
__global__ void transpose_x_kernel(const float* __restrict__ x) {
    int tc = blockIdx.x * blockDim.x + threadIdx.x;
    if (tc >= TC) return;
    __half2 h[8];
#pragma unroll
    for (int b = 0; b < 8; b++) {
        h[b] = __floats2half2_rn(x[(2 * b) * TC + tc], x[(2 * b + 1) * TC + tc]);
    }
    uint4* dst = reinterpret_cast<uint4*>(g_xTh + tc * BATCH);
    unsigned int* hu = reinterpret_cast<unsigned int*>(h);
    dst[0] = make_uint4(hu[0], hu[1], hu[2], hu[3]);
    dst[1] = make_uint4(hu[4], hu[5], hu[6], hu[7]);
}

// --------------------------------------------------------------------------
// Kernel 2: fused main + top patch layers.  (R10 schedule, data-only clamp)
// Block = 16 warps covering 32 consecutive p of one (s|t) row.
// Warp w owns tasks pA = w and pB = w+16: two INDEPENDENT gather->FMA
// chains per warp. Absent B task clamps its pointers to pA (warp-uniform
// SEL; duplicate gathers become L1 hits -> no extra L2/DRAM traffic and
// no control-flow/schedule perturbation).
// Lane = (q = lane>>2, c = lane&3):
//   - idx/W per chain: int4/float4 at [m*8+q] (128B per warp-load, 1 wf),
//   - gathers: quad q fetches row idx, lane reads 8B (batches 4c..4c+3),
//   - reduce via shfl_xor(4,8,16); q==0 lanes hold all 16 batches,
//   - padded smem stage; store: warp = batch, 32 lanes = 32 consecutive p
//     (128B rows, main repeated x8 along time).
// --------------------------------------------------------------------------
__global__ __launch_bounds__(THREADS, 2) void patchy_kernel(
    const float* __restrict__ W_main, const float* __restrict__ b_main,
    const float* __restrict__ W_top,  const float* __restrict__ b_top,
    const int*   __restrict__ idx_main, const int* __restrict__ idx_top,
    float* __restrict__ out)
{
    __shared__ float s_res[TPB * SB];

    const int tid  = threadIdx.x;
    const int w    = tid >> 5;       // warp id: local pA (compute) / batch (store)
    const int lane = tid & 31;
    const int q    = lane >> 2;      // quad: sub-index group
    const int c    = lane & 3;       // component: batches 4c..4c+3
    const bool is_main = (blockIdx.x < MAIN_BLOCKS);

    int st, p0, width;
    const int*   gi;
    const float* gw;
    const float* gb;
    if (is_main) {
        st    = blockIdx.x / MAIN_PB;
        p0    = (blockIdx.x - st * MAIN_PB) * TPB;
        width = min(TPB, NB_PATCH - p0);
        const long base = ((long)st * NB_PATCH + p0) * KDIM;
        gi = idx_main + base;
        gw = W_main   + base;
        gb = b_main   + st * NB_PATCH + p0;
    } else {
        const int b2 = blockIdx.x - MAIN_BLOCKS;
        st    = b2 >> 1;
        p0    = (b2 & 1) * TPB;
        width = min(TPB, P_TOP - p0);
        const long base = ((long)st * P_TOP + p0) * KDIM;
        gi = idx_top + base;
        gw = W_top   + base;
        gb = b_top   + st * P_TOP + p0;
    }

    // Two tasks per warp; absent task aliases pA (gathers become L1 hits).
    const int  pA   = w;
    const int  pB   = w + 16;
    const bool hasB = (pB < width);
    const int  pBc  = hasB ? pB : pA;

    {
        const int4*   ipA = reinterpret_cast<const int4*>(gi + pA  * KDIM);
        const int4*   ipB = reinterpret_cast<const int4*>(gi + pBc * KDIM);
        const float4* wpA = reinterpret_cast<const float4*>(gw + pA  * KDIM);
        const float4* wpB = reinterpret_cast<const float4*>(gw + pBc * KDIM);
        const uint2* __restrict__ xT2 = reinterpret_cast<const uint2*>(g_xTh);

        float4 accA = make_float4(0.f, 0.f, 0.f, 0.f);
        float4 accB = make_float4(0.f, 0.f, 0.f, 0.f);

#pragma unroll
        for (int m = 0; m < 4; m++) {
            // Interleaved independent chains: A's and B's gathers are both
            // in flight while either chain's FMAs execute.
            const int4 IA = ipA[m * 8 + q];
            const int4 IB = ipB[m * 8 + q];

            const uint2 gA0 = xT2[IA.x * 4 + c];
            const uint2 gA1 = xT2[IA.y * 4 + c];
            const uint2 gA2 = xT2[IA.z * 4 + c];
            const uint2 gA3 = xT2[IA.w * 4 + c];
            const uint2 gB0 = xT2[IB.x * 4 + c];
            const uint2 gB1 = xT2[IB.y * 4 + c];
            const uint2 gB2 = xT2[IB.z * 4 + c];
            const uint2 gB3 = xT2[IB.w * 4 + c];

            const float4 WA = wpA[m * 8 + q];
            const float4 WB = wpB[m * 8 + q];

            {
                const float2 l0 = __half22float2(*reinterpret_cast<const __half2*>(&gA0.x));
                const float2 h0 = __half22float2(*reinterpret_cast<const __half2*>(&gA0.y));
                accA.x = fmaf(l0.x, WA.x, accA.x); accA.y = fmaf(l0.y, WA.x, accA.y);
                accA.z = fmaf(h0.x, WA.x, accA.z); accA.w = fmaf(h0.y, WA.x, accA.w);
                const float2 l1 = __half22float2(*reinterpret_cast<const __half2*>(&gA1.x));
                const float2 h1 = __half22float2(*reinterpret_cast<const __half2*>(&gA1.y));
                accA.x = fmaf(l1.x, WA.y, accA.x); accA.y = fmaf(l1.y, WA.y, accA.y);
                accA.z = fmaf(h1.x, WA.y, accA.z); accA.w = fmaf(h1.y, WA.y, accA.w);
                const float2 l2 = __half22float2(*reinterpret_cast<const __half2*>(&gA2.x));
                const float2 h2 = __half22float2(*reinterpret_cast<const __half2*>(&gA2.y));
                accA.x = fmaf(l2.x, WA.z, accA.x); accA.y = fmaf(l2.y, WA.z, accA.y);
                accA.z = fmaf(h2.x, WA.z, accA.z); accA.w = fmaf(h2.y, WA.z, accA.w);
                const float2 l3 = __half22float2(*reinterpret_cast<const __half2*>(&gA3.x));
                const float2 h3 = __half22float2(*reinterpret_cast<const __half2*>(&gA3.y));
                accA.x = fmaf(l3.x, WA.w, accA.x); accA.y = fmaf(l3.y, WA.w, accA.y);
                accA.z = fmaf(h3.x, WA.w, accA.z); accA.w = fmaf(h3.y, WA.w, accA.w);
            }
            {
                const float2 l0 = __half22float2(*reinterpret_cast<const __half2*>(&gB0.x));
                const float2 h0 = __half22float2(*reinterpret_cast<const __half2*>(&gB0.y));
                accB.x = fmaf(l0.x, WB.x, accB.x); accB.y = fmaf(l0.y, WB.x, accB.y);
                accB.z = fmaf(h0.x, WB.x, accB.z); accB.w = fmaf(h0.y, WB.x, accB.w);
                const float2 l1 = __half22float2(*reinterpret_cast<const __half2*>(&gB1.x));
                const float2 h1 = __half22float2(*reinterpret_cast<const __half2*>(&gB1.y));
                accB.x = fmaf(l1.x, WB.y, accB.x); accB.y = fmaf(l1.y, WB.y, accB.y);
                accB.z = fmaf(h1.x, WB.y, accB.z); accB.w = fmaf(h1.y, WB.y, accB.w);
                const float2 l2 = __half22float2(*reinterpret_cast<const __half2*>(&gB2.x));
                const float2 h2 = __half22float2(*reinterpret_cast<const __half2*>(&gB2.y));
                accB.x = fmaf(l2.x, WB.z, accB.x); accB.y = fmaf(l2.y, WB.z, accB.y);
                accB.z = fmaf(h2.x, WB.z, accB.z); accB.w = fmaf(h2.y, WB.z, accB.w);
                const float2 l3 = __half22float2(*reinterpret_cast<const __half2*>(&gB3.x));
                const float2 h3 = __half22float2(*reinterpret_cast<const __half2*>(&gB3.y));
                accB.x = fmaf(l3.x, WB.w, accB.x); accB.y = fmaf(l3.y, WB.w, accB.y);
                accB.z = fmaf(h3.x, WB.w, accB.z); accB.w = fmaf(h3.y, WB.w, accB.w);
            }
        }

        // Reduce each chain across the 8 quads.
#pragma unroll
        for (int mask = 4; mask <= 16; mask <<= 1) {
            accA.x += __shfl_xor_sync(0xffffffffu, accA.x, mask);
            accA.y += __shfl_xor_sync(0xffffffffu, accA.y, mask);
            accA.z += __shfl_xor_sync(0xffffffffu, accA.z, mask);
            accA.w += __shfl_xor_sync(0xffffffffu, accA.w, mask);
            accB.x += __shfl_xor_sync(0xffffffffu, accB.x, mask);
            accB.y += __shfl_xor_sync(0xffffffffu, accB.y, mask);
            accB.z += __shfl_xor_sync(0xffffffffu, accB.z, mask);
            accB.w += __shfl_xor_sync(0xffffffffu, accB.w, mask);
        }

        if (q == 0) {
            {
                const float bias = gb[pA];
                float* r = s_res + pA * SB + c * 4;
                float vx = accA.x + bias, vy = accA.y + bias;
                float vz = accA.z + bias, vw = accA.w + bias;
                r[0] = (vx > 0.f) ? vx : 0.3f * vx;
                r[1] = (vy > 0.f) ? vy : 0.3f * vy;
                r[2] = (vz > 0.f) ? vz : 0.3f * vz;
                r[3] = (vw > 0.f) ? vw : 0.3f * vw;
            }
            if (hasB) {
                const float bias = gb[pB];
                float* r = s_res + pB * SB + c * 4;
                float vx = accB.x + bias, vy = accB.y + bias;
                float vz = accB.z + bias, vw = accB.w + bias;
                r[0] = (vx > 0.f) ? vx : 0.3f * vx;
                r[1] = (vy > 0.f) ? vy : 0.3f * vy;
                r[2] = (vz > 0.f) ? vz : 0.3f * vz;
                r[3] = (vw > 0.f) ? vw : 0.3f * vw;
            }
        }
    }
    __syncthreads();

    // ---- Coalesced store: warp = batch, 32 lanes = 32 consecutive p ----
    {
        if (lane < width) {
            const float y = s_res[lane * SB + w];   // stride-17 -> conflict-free
            if (is_main) {
                long o = (long)w * TLEN * P_OUT
                       + (long)(st * STRETCH) * P_OUT + p0 + lane;
#pragma unroll
                for (int r = 0; r < STRETCH; r++) {
                    out[o + (long)r * P_OUT] = y;   // 128B rows per STG
                }
            } else {
                out[(long)w * TLEN * P_OUT + (long)st * P_OUT
                    + NB_PATCH + p0 + lane] = y;
            }
        }
    }
}

// --------------------------------------------------------------------------
// Inputs (metadata order): x, W_main, b_main, W_top, b_top, idx_main, idx_top
// --------------------------------------------------------------------------
extern "C" void kernel_launch(void* const* d_in, const int* in_sizes, int n_in,
                              void* d_out, int out_size) {
    const float* x        = (const float*)d_in[0];
    const float* W_main   = (const float*)d_in[1];
    const float* b_main   = (const float*)d_in[2];
    const float* W_top    = (const float*)d_in[3];
    const float* b_top    = (const float*)d_in[4];
    const int*   idx_main = (const int*)  d_in[5];
    const int*   idx_top  = (const int*)  d_in[6];
    float* out = (float*)d_out;

    transpose_x_kernel<<<(TC + 255) / 256, 256>>>(x);

    patchy_kernel<<<ALL_BLOCKS, THREADS>>>(W_main, b_main, W_top, b_top,
                                           idx_main, idx_top, out);
}